// round 16
// baseline (speedup 1.0000x reference)
#include <cuda_runtime.h>
#include <cuda_fp16.h>
#include <cstdint>

#define NNODES 100000
#define NEDGES 1600000
#define SCANB  ((NNODES + 255) / 256)    // 391 scan tiles
#define NPAIRS ((NNODES + 1) / 2)        // 50000 node pairs
#define GTILES ((NNODES + 127) / 128)    // 782 gemm row-tiles

// ---- scratch (device globals; no allocation allowed) ----
__device__ int      g_counts[NNODES];    // zero at entry (static init / phase-4 clean)
__device__ int      g_fill[NNODES];
__device__ int      g_rowptr[NNODES + 1];
__device__ int      g_partial[SCANB];
__device__ int2     g_edge[NEDGES];      // {src, __float_as_int(w)}
__device__ __half   g_suph[(size_t)NNODES * 64];
__device__ float    g_h[(size_t)NNODES * 64];
__device__ unsigned g_bar_cnt = 0;       // barrier arrive counter (0 between barriers)
__device__ unsigned g_bar_gen = 0;       // barrier generation (persists across execs)

// ---------------------------------------------------------------- grid barrier
// Sense via monotonically increasing generation. All blocks co-resident
// (grid sized by occupancy API). gpu-scope fences provide release/acquire AND
// L1D invalidation (CCTL.IVALL) so cross-phase data is never stale.
__device__ __forceinline__ void gsync(unsigned& gen) {
    __syncthreads();
    if (threadIdx.x == 0) {
        __threadfence();
        unsigned target = gen + 1;
        unsigned t = atomicAdd(&g_bar_cnt, 1);
        if (t == gridDim.x - 1) {
            g_bar_cnt = 0;                     // safe: none can arrive at next
            __threadfence();                   //   barrier until gen bumps
            atomicExch(&g_bar_gen, target);
        } else {
            while (atomicAdd(&g_bar_gen, 0) < target) __nanosleep(64);
        }
        __threadfence();
    }
    __syncthreads();
    gen++;
}

// ---------------------------------------------------------------- HMMA helpers
__device__ __forceinline__ unsigned smem_u32(const void* p) {
    return (unsigned)__cvta_generic_to_shared(p);
}
__device__ __forceinline__ void ldsm_x4(unsigned& a0, unsigned& a1,
                                        unsigned& a2, unsigned& a3, unsigned addr) {
    asm volatile("ldmatrix.sync.aligned.m8n8.x4.shared.b16 {%0,%1,%2,%3}, [%4];"
                 : "=r"(a0), "=r"(a1), "=r"(a2), "=r"(a3) : "r"(addr));
}
__device__ __forceinline__ void ldsm_x2t(unsigned& b0, unsigned& b1, unsigned addr) {
    asm volatile("ldmatrix.sync.aligned.m8n8.x2.trans.shared.b16 {%0,%1}, [%2];"
                 : "=r"(b0), "=r"(b1) : "r"(addr));
}
__device__ __forceinline__ void mma16816(float* c, unsigned a0, unsigned a1,
                                         unsigned a2, unsigned a3,
                                         unsigned b0, unsigned b1) {
    asm volatile(
        "mma.sync.aligned.m16n8k16.row.col.f32.f16.f16.f32 "
        "{%0,%1,%2,%3},{%4,%5,%6,%7},{%8,%9},{%0,%1,%2,%3};"
        : "+f"(c[0]), "+f"(c[1]), "+f"(c[2]), "+f"(c[3])
        : "r"(a0), "r"(a1), "r"(a2), "r"(a3), "r"(b0), "r"(b1));
}
__device__ __forceinline__ void h4_to_f4(uint2 u, float2& lo, float2& hi) {
    __half2 ha = *reinterpret_cast<__half2*>(&u.x);
    __half2 hb = *reinterpret_cast<__half2*>(&u.y);
    lo = __half22float2(ha);
    hi = __half22float2(hb);
}

// ---------------------------------------------------------------- gemm phase
// Yh[NNODES,M] (fp16) = X[NNODES,K] (fp32, via __ldcg) @ W[K,M] (fp32).
// Block-stride over 128-row tiles. fsm reused across phases.
template <int K, int M>
__device__ void gemm_phase(const float* __restrict__ X,
                           const float* __restrict__ W,
                           __half* __restrict__ Yh, char* fsm) {
    constexpr int KP = K + 8;
    constexpr int MP = M + 8;
    constexpr int NC = M / 8;
    __half* Xs = (__half*)fsm;          // [128][KP]
    __half* Ws = Xs + 128 * KP;         // [K][MP]
    const int tid  = threadIdx.x;
    const int wid  = tid >> 5;
    const int lane = tid & 31;

    for (int tile = blockIdx.x; tile < GTILES; tile += gridDim.x) {
        const int rowBase = tile * 128;
        for (int i = tid; i < 128 * (K / 2); i += 256) {
            int r = i / (K / 2), c2 = i % (K / 2);
            int grow = rowBase + r;
            float2 v = (grow < NNODES)
                     ? __ldcg(&((const float2*)X)[(size_t)grow * (K / 2) + c2])
                     : make_float2(0.f, 0.f);
            *(__half2*)&Xs[r * KP + c2 * 2] = __floats2half2_rn(v.x, v.y);
        }
        for (int i = tid; i < K * (M / 2); i += 256) {
            int k = i / (M / 2), c2 = i % (M / 2);
            float2 v = ((const float2*)W)[i];
            *(__half2*)&Ws[k * MP + c2 * 2] = __floats2half2_rn(v.x, v.y);
        }
        __syncthreads();

        const int rw = wid * 16;
        float acc[NC][4];
#pragma unroll
        for (int nc = 0; nc < NC; nc++) {
#pragma unroll
            for (int q = 0; q < 4; q++) acc[nc][q] = 0.f;
        }
#pragma unroll
        for (int kc = 0; kc < K / 16; kc++) {
            unsigned a0, a1, a2, a3;
            unsigned aaddr = smem_u32(&Xs[(rw + (lane & 15)) * KP + kc * 16 + (lane >> 4) * 8]);
            ldsm_x4(a0, a1, a2, a3, aaddr);
#pragma unroll
            for (int nc = 0; nc < NC; nc++) {
                unsigned b0, b1;
                unsigned baddr = smem_u32(&Ws[(kc * 16 + (lane & 15)) * MP + nc * 8]);
                ldsm_x2t(b0, b1, baddr);
                mma16816(acc[nc], a0, a1, a2, a3, b0, b1);
            }
        }

        int rA = rowBase + rw + (lane >> 2);
        int rB = rA + 8;
        int colb = (lane & 3) * 2;
#pragma unroll
        for (int nc = 0; nc < NC; nc++) {
            int col = nc * 8 + colb;
            if (rA < NNODES)
                *(__half2*)&Yh[(size_t)rA * M + col] = __floats2half2_rn(acc[nc][0], acc[nc][1]);
            if (rB < NNODES)
                *(__half2*)&Yh[(size_t)rB * M + col] = __floats2half2_rn(acc[nc][2], acc[nc][3]);
        }
        __syncthreads();    // smem safe to restage for next tile
    }
}

// ---------------------------------------------------------------- agg phases
// TWO nodes per warp; lane owns 4 features via one 8B fp16 __ldcg gather.
__device__ void agg64_phase(const float* __restrict__ bias,
                            float* hout, const float* resid, int has_resid) {
    const int totalWarps = gridDim.x * 8;
    const int gwid = blockIdx.x * 8 + (threadIdx.x >> 5);
    const int lane = threadIdx.x & 31;
    const int hf = lane >> 4, sub = lane & 15;
    for (int gw = gwid; gw < NPAIRS; gw += totalWarps) {
        int node = gw * 2 + hf;
        int e   = __ldcg(&g_rowptr[node]);
        int end = __ldcg(&g_rowptr[node + 1]);
        float4 a = make_float4(0.f, 0.f, 0.f, 0.f);
        for (; e + 4 <= end; e += 4) {
            uint2 e0 = __ldcg((const uint2*)&g_edge[e]);
            uint2 e1 = __ldcg((const uint2*)&g_edge[e + 1]);
            uint2 e2 = __ldcg((const uint2*)&g_edge[e + 2]);
            uint2 e3 = __ldcg((const uint2*)&g_edge[e + 3]);
            uint2 r0 = __ldcg((const uint2*)&g_suph[(size_t)e0.x * 64 + sub * 4]);
            uint2 r1 = __ldcg((const uint2*)&g_suph[(size_t)e1.x * 64 + sub * 4]);
            uint2 r2 = __ldcg((const uint2*)&g_suph[(size_t)e2.x * 64 + sub * 4]);
            uint2 r3 = __ldcg((const uint2*)&g_suph[(size_t)e3.x * 64 + sub * 4]);
            float w0 = __uint_as_float(e0.y), w1 = __uint_as_float(e1.y);
            float w2 = __uint_as_float(e2.y), w3 = __uint_as_float(e3.y);
            float2 fa, fb;
            h4_to_f4(r0, fa, fb);
            a.x = fmaf(fa.x, w0, a.x); a.y = fmaf(fa.y, w0, a.y);
            a.z = fmaf(fb.x, w0, a.z); a.w = fmaf(fb.y, w0, a.w);
            h4_to_f4(r1, fa, fb);
            a.x = fmaf(fa.x, w1, a.x); a.y = fmaf(fa.y, w1, a.y);
            a.z = fmaf(fb.x, w1, a.z); a.w = fmaf(fb.y, w1, a.w);
            h4_to_f4(r2, fa, fb);
            a.x = fmaf(fa.x, w2, a.x); a.y = fmaf(fa.y, w2, a.y);
            a.z = fmaf(fb.x, w2, a.z); a.w = fmaf(fb.y, w2, a.w);
            h4_to_f4(r3, fa, fb);
            a.x = fmaf(fa.x, w3, a.x); a.y = fmaf(fa.y, w3, a.y);
            a.z = fmaf(fb.x, w3, a.z); a.w = fmaf(fb.y, w3, a.w);
        }
        for (; e < end; e++) {
            uint2 ed = __ldcg((const uint2*)&g_edge[e]);
            uint2 rv = __ldcg((const uint2*)&g_suph[(size_t)ed.x * 64 + sub * 4]);
            float w = __uint_as_float(ed.y);
            float2 fa, fb; h4_to_f4(rv, fa, fb);
            a.x = fmaf(fa.x, w, a.x); a.y = fmaf(fa.y, w, a.y);
            a.z = fmaf(fb.x, w, a.z); a.w = fmaf(fb.y, w, a.w);
        }
        float4 bv = ((const float4*)bias)[sub];
        a.x = fmaxf(a.x + bv.x, 0.f);
        a.y = fmaxf(a.y + bv.y, 0.f);
        a.z = fmaxf(a.z + bv.z, 0.f);
        a.w = fmaxf(a.w + bv.w, 0.f);
        if (has_resid) {           // resid aliases hout: same-element RMW only
            float4 rv = __ldcg((const float4*)(resid + (size_t)node * 64) + sub);
            a.x += rv.x; a.y += rv.y; a.z += rv.z; a.w += rv.w;
        }
        ((float4*)(hout + (size_t)node * 64))[sub] = a;
    }
}

__device__ void agg40_phase(const float* __restrict__ bias, float* __restrict__ out) {
    const int totalWarps = gridDim.x * 8;
    const int gwid = blockIdx.x * 8 + (threadIdx.x >> 5);
    const int lane = threadIdx.x & 31;
    const int hf = lane >> 4, sub = lane & 15;
    const bool act = (sub < 10);
    for (int gw = gwid; gw < NPAIRS; gw += totalWarps) {
        int node = gw * 2 + hf;
        int e   = __ldcg(&g_rowptr[node]);
        int end = __ldcg(&g_rowptr[node + 1]);
        float4 a = make_float4(0.f, 0.f, 0.f, 0.f);
        for (; e + 4 <= end; e += 4) {
            uint2 e0 = __ldcg((const uint2*)&g_edge[e]);
            uint2 e1 = __ldcg((const uint2*)&g_edge[e + 1]);
            uint2 e2 = __ldcg((const uint2*)&g_edge[e + 2]);
            uint2 e3 = __ldcg((const uint2*)&g_edge[e + 3]);
            uint2 r0 = make_uint2(0, 0), r1 = r0, r2 = r0, r3 = r0;
            if (act) {
                r0 = __ldcg((const uint2*)&g_suph[(size_t)e0.x * 40 + sub * 4]);
                r1 = __ldcg((const uint2*)&g_suph[(size_t)e1.x * 40 + sub * 4]);
                r2 = __ldcg((const uint2*)&g_suph[(size_t)e2.x * 40 + sub * 4]);
                r3 = __ldcg((const uint2*)&g_suph[(size_t)e3.x * 40 + sub * 4]);
            }
            float w0 = __uint_as_float(e0.y), w1 = __uint_as_float(e1.y);
            float w2 = __uint_as_float(e2.y), w3 = __uint_as_float(e3.y);
            float2 fa, fb;
            h4_to_f4(r0, fa, fb);
            a.x = fmaf(fa.x, w0, a.x); a.y = fmaf(fa.y, w0, a.y);
            a.z = fmaf(fb.x, w0, a.z); a.w = fmaf(fb.y, w0, a.w);
            h4_to_f4(r1, fa, fb);
            a.x = fmaf(fa.x, w1, a.x); a.y = fmaf(fa.y, w1, a.y);
            a.z = fmaf(fb.x, w1, a.z); a.w = fmaf(fb.y, w1, a.w);
            h4_to_f4(r2, fa, fb);
            a.x = fmaf(fa.x, w2, a.x); a.y = fmaf(fa.y, w2, a.y);
            a.z = fmaf(fb.x, w2, a.z); a.w = fmaf(fb.y, w2, a.w);
            h4_to_f4(r3, fa, fb);
            a.x = fmaf(fa.x, w3, a.x); a.y = fmaf(fa.y, w3, a.y);
            a.z = fmaf(fb.x, w3, a.z); a.w = fmaf(fb.y, w3, a.w);
        }
        for (; e < end; e++) {
            uint2 ed = __ldcg((const uint2*)&g_edge[e]);
            uint2 rv = make_uint2(0, 0);
            if (act) rv = __ldcg((const uint2*)&g_suph[(size_t)ed.x * 40 + sub * 4]);
            float w = __uint_as_float(ed.y);
            float2 fa, fb; h4_to_f4(rv, fa, fb);
            a.x = fmaf(fa.x, w, a.x); a.y = fmaf(fa.y, w, a.y);
            a.z = fmaf(fb.x, w, a.z); a.w = fmaf(fb.y, w, a.w);
        }
        if (act) {
            float4 bv = ((const float4*)bias)[sub];
            a.x += bv.x; a.y += bv.y; a.z += bv.z; a.w += bv.w;
        }
        float m = act ? fmaxf(fmaxf(a.x, a.y), fmaxf(a.z, a.w)) : -3.4e38f;
#pragma unroll
        for (int o = 8; o; o >>= 1) m = fmaxf(m, __shfl_xor_sync(0xffffffffu, m, o, 16));
        float ssum = act ? (__expf(a.x - m) + __expf(a.y - m) +
                            __expf(a.z - m) + __expf(a.w - m)) : 0.f;
#pragma unroll
        for (int o = 8; o; o >>= 1) ssum += __shfl_xor_sync(0xffffffffu, ssum, o, 16);
        float L = m + __logf(ssum);
        if (act) {
            float4 o4; o4.x = a.x - L; o4.y = a.y - L; o4.z = a.z - L; o4.w = a.w - L;
            ((float4*)(out + (size_t)node * 40))[sub] = o4;
        }
    }
}

// ---------------------------------------------------------------- fused kernel
__global__ __launch_bounds__(256)
void fused_kernel(const float* __restrict__ x,
                  const int* __restrict__ src, const int* __restrict__ tgt,
                  const float* __restrict__ mw,
                  const float* __restrict__ W0, const float* __restrict__ b0,
                  const float* __restrict__ W1, const float* __restrict__ b1,
                  const float* __restrict__ W2, const float* __restrict__ b2,
                  const float* __restrict__ W3, const float* __restrict__ b3,
                  float* __restrict__ out) {
    extern __shared__ char fsm[];
    const int tid = threadIdx.x;
    unsigned gen = 0;
    if (tid == 0) gen = atomicAdd(&g_bar_gen, 0);   // current generation

    void* ph; asm("" : : );  // (no-op)
    __half* sup = g_suph;
    float*  h   = g_h;

    // ---- phase 1: histogram of tgt (counts pre-zeroed) ----
    for (int e = blockIdx.x * 256 + tid; e < NEDGES; e += gridDim.x * 256)
        atomicAdd(&g_counts[tgt[e]], 1);
    gsync(gen);

    // ---- phase 2: per-tile sums ----
    {
        int* s = (int*)fsm;
        for (int tile = blockIdx.x; tile < SCANB; tile += gridDim.x) {
            int i = tile * 256 + tid;
            s[tid] = (i < NNODES) ? __ldcg(&g_counts[i]) : 0;
            __syncthreads();
            for (int off = 128; off; off >>= 1) {
                if (tid < off) s[tid] += s[tid + off];
                __syncthreads();
            }
            if (tid == 0) g_partial[tile] = s[0];
            __syncthreads();
        }
    }
    gsync(gen);

    // ---- phase 3: block 0 scans the 391 partials (ping-pong, 512 slots) ----
    if (blockIdx.x == 0) {
        int* A = (int*)fsm;
        int* B = A + 512;
        A[tid]       = (tid < SCANB) ? __ldcg(&g_partial[tid]) : 0;
        A[tid + 256] = (tid + 256 < SCANB) ? __ldcg(&g_partial[tid + 256]) : 0;
        __syncthreads();
        int* pin = A; int* pout = B;
        for (int off = 1; off < 512; off <<= 1) {
            pout[tid] = pin[tid] + ((tid >= off) ? pin[tid - off] : 0);
            int j = tid + 256;
            pout[j] = pin[j] + ((j >= off) ? pin[j - off] : 0);
            __syncthreads();
            int* t2 = pin; pin = pout; pout = t2;
        }
        if (tid < SCANB)       g_partial[tid]       = (tid == 0) ? 0 : pin[tid - 1];
        if (tid + 256 < SCANB) g_partial[tid + 256] = pin[tid + 255];
    }
    gsync(gen);

    // ---- phase 4: emit rowptr + seed fill cursor + self-clean counts ----
    {
        int* s = (int*)fsm;
        for (int tile = blockIdx.x; tile < SCANB; tile += gridDim.x) {
            int i = tile * 256 + tid;
            int c = (i < NNODES) ? __ldcg(&g_counts[i]) : 0;
            s[tid] = c;
            __syncthreads();
            for (int off = 1; off < 256; off <<= 1) {
                int v = s[tid];
                int add = (tid >= off) ? s[tid - off] : 0;
                __syncthreads();
                s[tid] = v + add;
                __syncthreads();
            }
            if (i < NNODES) {
                int rp = __ldcg(&g_partial[tile]) + s[tid] - c;
                g_rowptr[i] = rp;
                g_fill[i]   = rp;
                g_counts[i] = 0;
            }
            __syncthreads();
        }
        if (blockIdx.x == 0 && tid == 0) g_rowptr[NNODES] = NEDGES;
    }
    gsync(gen);

    // ---- phase 5: scatter edges into CSR order ----
    for (int e = blockIdx.x * 256 + tid; e < NEDGES; e += gridDim.x * 256) {
        int pos = atomicAdd(&g_fill[tgt[e]], 1);
        int2 pk; pk.x = src[e]; pk.y = __float_as_int(mw[e]);
        g_edge[pos] = pk;
    }
    gsync(gen);

    // ---- layer 0: h = relu(A @ (x W0) + b0) ----
    gemm_phase<128, 64>(x, W0, sup, fsm);
    gsync(gen);
    agg64_phase(b0, h, nullptr, 0);
    gsync(gen);
    // ---- layer 1: h = relu(A @ (h W1) + b1) + h ----
    gemm_phase<64, 64>(h, W1, sup, fsm);
    gsync(gen);
    agg64_phase(b1, h, h, 1);
    gsync(gen);
    // ---- layer 2 ----
    gemm_phase<64, 64>(h, W2, sup, fsm);
    gsync(gen);
    agg64_phase(b2, h, h, 1);
    gsync(gen);
    // ---- layer 3: out = log_softmax(A @ (h W3) + b3) ----
    gemm_phase<64, 40>(h, W3, sup, fsm);
    gsync(gen);
    agg40_phase(b3, out);
}

// ---------------------------------------------------------------- launch
extern "C" void kernel_launch(void* const* d_in, const int* in_sizes, int n_in,
                              void* d_out, int out_size) {
    const float* x   = (const float*)d_in[0];
    const int*   src = (const int*)d_in[1];
    const int*   tgt = (const int*)d_in[2];
    const float* mw  = (const float*)d_in[3];
    const float* W0  = (const float*)d_in[4];  const float* b0 = (const float*)d_in[5];
    const float* W1  = (const float*)d_in[6];  const float* b1 = (const float*)d_in[7];
    const float* W2  = (const float*)d_in[8];  const float* b2 = (const float*)d_in[9];
    const float* W3  = (const float*)d_in[10]; const float* b3 = (const float*)d_in[11];
    float* out = (float*)d_out;

    const int SMEM = (128 * 136 + 128 * 72) * 2;   // 53248 (max over phases)
    cudaFuncSetAttribute(fused_kernel, cudaFuncAttributeMaxDynamicSharedMemorySize, SMEM);

    int dev = 0;
    cudaGetDevice(&dev);
    int smCount = 148;
    cudaDeviceGetAttribute(&smCount, cudaDevAttrMultiProcessorCount, dev);
    int bpsm = 0;
    cudaOccupancyMaxActiveBlocksPerMultiprocessor(&bpsm, fused_kernel, 256, SMEM);
    if (bpsm < 1) bpsm = 1;
    int grid = smCount * bpsm;   // exactly co-resident (RR placement: bpsm per SM)

    fused_kernel<<<grid, 256, SMEM>>>(x, src, tgt, mw,
                                      W0, b0, W1, b1, W2, b2, W3, b3, out);
}